// round 16
// baseline (speedup 1.0000x reference)
#include <cuda_runtime.h>
#include <math.h>

#define N_    1024
#define H_    12
#define C1_   384
#define C2_   128
#define COUT_ 384
#define NPROJ 1152
#define NFEAT 2112
#define QB    4
#define TM    16
#define NT    (N_ / TM)
#define BUFF  (QB * TM * C2_)      // 8192 floats = 32KB per buffer

#define W2DS 0.5773502691896258f
#define SCW  0.14433756729740643f
#define PTW  0.1360827634879543f

typedef unsigned long long u64;

__device__ __forceinline__ void fma2(u64& acc, u64 a, u64 b) {
    asm("fma.rn.f32x2 %0, %1, %2, %0;" : "+l"(acc) : "l"(a), "l"(b));
}
__device__ __forceinline__ void mul2(u64& a, u64 b) {
    asm("mul.rn.f32x2 %0, %0, %1;" : "+l"(a) : "l"(b));
}
__device__ __forceinline__ u64 pack2(float a) {
    u64 r;
    asm("mov.b64 %0, {%1, %1};" : "=l"(r) : "f"(a));
    return r;
}
__device__ __forceinline__ unsigned smem_u32(const void* p) {
    return (unsigned)__cvta_generic_to_shared(p);
}
__device__ __forceinline__ void bulk_cp(unsigned dst, const void* src,
                                        unsigned bytes, unsigned mbar) {
    asm volatile(
        "cp.async.bulk.shared::cta.global.mbarrier::complete_tx::bytes "
        "[%0], [%1], %2, [%3];"
        :: "r"(dst), "l"(src), "r"(bytes), "r"(mbar) : "memory");
}
__device__ __forceinline__ void mbar_init(unsigned mbar, unsigned cnt) {
    asm volatile("mbarrier.init.shared.b64 [%0], %1;" :: "r"(mbar), "r"(cnt) : "memory");
}
__device__ __forceinline__ void mbar_expect_tx(unsigned mbar, unsigned bytes) {
    asm volatile("mbarrier.arrive.expect_tx.shared.b64 _, [%0], %1;"
                 :: "r"(mbar), "r"(bytes) : "memory");
}
__device__ __forceinline__ void mbar_wait(unsigned mbar, unsigned parity) {
    asm volatile(
        "{\n\t"
        ".reg .pred P1;\n\t"
        "WAIT_LOOP_%=:\n\t"
        "mbarrier.try_wait.parity.acquire.cta.shared::cta.b64 P1, [%0], %1, 0x989680;\n\t"
        "@P1 bra.uni WAIT_DONE_%=;\n\t"
        "bra.uni WAIT_LOOP_%=;\n\t"
        "WAIT_DONE_%=:\n\t"
        "}"
        :: "r"(mbar), "r"(parity) : "memory");
}

// ---------------- scratch ----------------
__device__ float g_proj [N_ * NPROJ];
__device__ float g_qpt  [N_ * 144];
__device__ float g_kpt  [N_ * 144];
__device__ float g_vpt  [N_ * 288];
__device__ float g_qaug [N_ * H_ * 32];
__device__ float g_kaug [N_ * H_ * 32];
__device__ float g_L    [(long)N_ * H_ * 1024];   // raw qk logits (masked)
__device__ float g_vm   [(long)N_ * H_ * 64];
__device__ float g_feat [(long)N_ * NFEAT];

// ---------------- kernel A: fused projection GEMM ----------------
__global__ __launch_bounds__(256) void proj_gemm_kernel(
    const float* __restrict__ A,
    const float* __restrict__ wq,  const float* __restrict__ bq,
    const float* __restrict__ wkv, const float* __restrict__ bkv,
    const float* __restrict__ wqp, const float* __restrict__ bqp,
    const float* __restrict__ wkvp,const float* __restrict__ bkvp)
{
    __shared__ float As[16][64];
    __shared__ float Bs[16][68];
    int bm = blockIdx.x * 64, bn = blockIdx.y * 64;
    int tid = threadIdx.x;
    int tx = tid & 15, ty = tid >> 4;
    int lm = tid >> 2, lk4 = (tid & 3) * 4;
    int bk = tid >> 4, bn4 = (tid & 15) * 4;
    u64 acc01[4] = {0,0,0,0}, acc23[4] = {0,0,0,0};

    for (int k0 = 0; k0 < C1_; k0 += 16) {
        float4 av = *(const float4*)&A[(bm + lm) * C1_ + k0 + lk4];
        As[lk4+0][lm] = av.x; As[lk4+1][lm] = av.y;
        As[lk4+2][lm] = av.z; As[lk4+3][lm] = av.w;
        int kg = k0 + bk;
        #pragma unroll
        for (int jj = 0; jj < 4; jj++) {
            int j = bn + bn4 + jj;
            float v;
            if      (j < 192) v = wq  [kg * 192 + j];
            else if (j < 576) v = wkv [kg * 384 + (j - 192)];
            else if (j < 720) v = wqp [kg * 144 + (j - 576)];
            else              v = wkvp[kg * 432 + (j - 720)];
            Bs[bk][bn4 + jj] = v;
        }
        __syncthreads();
        #pragma unroll
        for (int kk = 0; kk < 16; kk++) {
            float4 a4 = *(const float4*)&As[kk][ty * 4];
            ulonglong2 b2 = *(const ulonglong2*)&Bs[kk][tx * 4];
            float a[4] = {a4.x, a4.y, a4.z, a4.w};
            #pragma unroll
            for (int i = 0; i < 4; i++) {
                u64 ai = pack2(a[i]);
                fma2(acc01[i], ai, b2.x);
                fma2(acc23[i], ai, b2.y);
            }
        }
        __syncthreads();
    }
    #pragma unroll
    for (int i = 0; i < 4; i++) {
        float2 lo = *(float2*)&acc01[i];
        float2 hi = *(float2*)&acc23[i];
        float accv[4] = {lo.x, lo.y, hi.x, hi.y};
        #pragma unroll
        for (int j = 0; j < 4; j++) {
            int jg = bn + tx * 4 + j;
            float bias;
            if      (jg < 192) bias = bq  [jg];
            else if (jg < 576) bias = bkv [jg - 192];
            else if (jg < 720) bias = bqp [jg - 576];
            else               bias = bkvp[jg - 720];
            g_proj[(bm + ty * 4 + i) * NPROJ + jg] = accv[j] + bias;
        }
    }
}

// ---------------- kernel B: transform + aug + merged v ----------------
__global__ __launch_bounds__(192) void transform_kernel(
    const float* __restrict__ rot, const float* __restrict__ trans,
    const float* __restrict__ tpw)
{
    int n = blockIdx.x;
    int tid = threadIdx.x;
    __shared__ float sn2[192];

    const float* pr = g_proj + n * NPROJ;
    float r00 = rot[n*9+0], r01 = rot[n*9+1], r02 = rot[n*9+2];
    float r10 = rot[n*9+3], r11 = rot[n*9+4], r12 = rot[n*9+5];
    float r20 = rot[n*9+6], r21 = rot[n*9+7], r22 = rot[n*9+8];
    float t0 = trans[n*3+0], t1 = trans[n*3+1], t2 = trans[n*3+2];

    float nrm = 0.f;
    if (tid < 48) {
        int pp = tid;
        float px = pr[576 +       pp];
        float py = pr[576 +  48 + pp];
        float pz = pr[576 +  96 + pp];
        float gx = r00*px + r01*py + r02*pz + t0;
        float gy = r10*px + r11*py + r12*pz + t1;
        float gz = r20*px + r21*py + r22*pz + t2;
        int h = pp >> 2, p = pp & 3;
        float* o = g_qpt + n * 144 + h * 12 + p * 3;
        o[0] = gx; o[1] = gy; o[2] = gz;
        nrm = gx*gx + gy*gy + gz*gz;
    } else {
        int pp = tid - 48;
        float px = pr[720 +       pp];
        float py = pr[720 + 144 + pp];
        float pz = pr[720 + 288 + pp];
        float gx = r00*px + r01*py + r02*pz + t0;
        float gy = r10*px + r11*py + r12*pz + t1;
        float gz = r20*px + r21*py + r22*pz + t2;
        int h = pp / 12, r = pp % 12;
        if (r < 4) {
            float* o = g_kpt + n * 144 + h * 12 + r * 3;
            o[0] = gx; o[1] = gy; o[2] = gz;
            nrm = gx*gx + gy*gy + gz*gz;
        } else {
            float* o = g_vpt + n * 288 + h * 24 + (r - 4) * 3;
            o[0] = gx; o[1] = gy; o[2] = gz;
        }
    }
    sn2[tid] = nrm;
    __syncthreads();
    if (tid < H_) {
        int h = tid;
        float q2 = 0.f, k2 = 0.f;
        #pragma unroll
        for (int p = 0; p < 4; p++) q2 += sn2[h * 4 + p];
        #pragma unroll
        for (int r = 0; r < 4; r++) k2 += sn2[48 + h * 12 + r];

        float tp = tpw[h];
        float spv = tp > 20.f ? tp : log1pf(__expf(tp));
        float pw = PTW * spv;

        float* qa = g_qaug + (n * H_ + h) * 32;
        float* ka = g_kaug + (n * H_ + h) * 32;
        #pragma unroll
        for (int c = 0; c < 16; c++) {
            qa[c] = SCW * pr[h * 16 + c];
            ka[c] = pr[192 + h * 32 + c];
        }
        #pragma unroll
        for (int c = 0; c < 12; c++) {
            qa[16 + c] = pw * g_qpt[n * 144 + h * 12 + c];
            ka[16 + c] = g_kpt[n * 144 + h * 12 + c];
        }
        qa[28] = -0.5f * pw * q2; qa[29] = 1.f; qa[30] = 0.f; qa[31] = 0.f;
        ka[28] = 1.f; ka[29] = -0.5f * pw * k2; ka[30] = 0.f; ka[31] = 0.f;

        float2* vm = (float2*)&g_vm[((long)n * H_ + h) * 64];
        #pragma unroll
        for (int j = 0; j < 8; j++)
            vm[j] = make_float2(pr[192 + h * 32 + 16 + 2*j],
                                pr[192 + h * 32 + 16 + 2*j + 1]);
        #pragma unroll
        for (int j = 8; j < 20; j++)
            vm[j] = make_float2(g_vpt[n * 288 + h * 24 + 2*(j-8)],
                                g_vpt[n * 288 + h * 24 + 2*(j-8) + 1]);
        #pragma unroll
        for (int j = 20; j < 32; j++)
            vm[j] = make_float2(0.f, 0.f);
    }
}

// ---------------- kernel C: qk GEMM + mask -> g_L (raw logits, f32x2) ----------------
__global__ __launch_bounds__(256) void qk_kernel(const float* __restrict__ mask)
{
    __shared__ float Aq[32][68];
    __shared__ float Bk[32][68];
    int h  = blockIdx.z;
    int nb = blockIdx.y * 64, mb = blockIdx.x * 64;
    int tid = threadIdx.x;

    for (int i = tid; i < 64 * 8; i += 256) {
        int row = i >> 3, k4 = (i & 7) * 4;
        float4 q = *(const float4*)&g_qaug[((nb + row) * H_ + h) * 32 + k4];
        Aq[k4+0][row] = q.x; Aq[k4+1][row] = q.y; Aq[k4+2][row] = q.z; Aq[k4+3][row] = q.w;
        float4 k = *(const float4*)&g_kaug[((mb + row) * H_ + h) * 32 + k4];
        Bk[k4+0][row] = k.x; Bk[k4+1][row] = k.y; Bk[k4+2][row] = k.z; Bk[k4+3][row] = k.w;
    }
    __syncthreads();

    int tx = tid & 15, ty = tid >> 4;
    u64 acc01[4] = {0,0,0,0}, acc23[4] = {0,0,0,0};
    #pragma unroll
    for (int k = 0; k < 32; k++) {
        float4 a4 = *(const float4*)&Aq[k][ty * 4];
        ulonglong2 b2 = *(const ulonglong2*)&Bk[k][tx * 4];
        float a[4] = {a4.x, a4.y, a4.z, a4.w};
        #pragma unroll
        for (int i = 0; i < 4; i++) {
            u64 ai = pack2(a[i]);
            fma2(acc01[i], ai, b2.x);
            fma2(acc23[i], ai, b2.y);
        }
    }
    float mm[4], mn[4];
    #pragma unroll
    for (int j = 0; j < 4; j++) mm[j] = mask[mb + tx * 4 + j];
    #pragma unroll
    for (int i = 0; i < 4; i++) mn[i] = mask[nb + ty * 4 + i];

    #pragma unroll
    for (int i = 0; i < 4; i++) {
        float2 lo = *(float2*)&acc01[i];
        float2 hi = *(float2*)&acc23[i];
        float4 L4;
        L4.x = lo.x - 100000.f * (1.f - mn[i] * mm[0]);
        L4.y = lo.y - 100000.f * (1.f - mn[i] * mm[1]);
        L4.z = hi.x - 100000.f * (1.f - mn[i] * mm[2]);
        L4.w = hi.y - 100000.f * (1.f - mn[i] * mm[3]);
        *(float4*)&g_L[((long)(nb + ty * 4 + i) * H_ + h) * N_ + mb + tx * 4] = L4;
    }
}

// ---------------- kernel D: fused attention (a2d in-kernel, conflict-free) ----------------
__global__ void __launch_bounds__(384, 2) attn_kernel(
    const float* __restrict__ in2d,
    const float* __restrict__ rot, const float* __restrict__ trans,
    const float* __restrict__ w2d, const float* __restrict__ b2d)
{
    extern __shared__ float sm[];
    float* s2d  = sm;                      // 2 * 8192
    float* spH  = sm + 2 * BUFF;           // 12*16*8 = 1536
    float* sw2  = spH + H_ * TM * 8;       // 12*128 = 1536  [h][c]
    float* sred = sw2 + H_ * C2_;          // 4*12*16 = 768
    float* sb2  = sred + QB * H_ * TM;     // 12
    float* sinv = sb2 + H_;                // 48
    u64*   mbar = (u64*)(sinv + QB * H_);  // 2

    int tid  = threadIdx.x;
    int h    = tid >> 5;
    int lane = tid & 31;
    int n0   = blockIdx.x * QB;

    int c4 = tid & 31;
    int hp = (tid >> 5) % 6;
    int mq = tid / 192;
    int h0 = hp * 2;

    // phase-2 role (tid < 256)
    int q2i = tid >> 6;
    int r2  = (tid >> 2) & 15;
    int u2  = tid & 3;

    unsigned s2d_sm  = smem_u32(s2d);
    unsigned mbar_sm = smem_u32(mbar);
    const u64* vm64 = (const u64*)g_vm;
    const ulonglong2* pbase = (const ulonglong2*)spH;   // [h*16+mi][2]
    const ulonglong2* swu2  = (const ulonglong2*)sw2;

    for (int i = tid; i < H_ * C2_; i += 384)
        sw2[i] = w2d[(i & 127) * H_ + (i >> 7)] * W2DS;
    if (tid < H_) sb2[tid] = b2d[tid] * W2DS;

    if (tid == 0) {
        mbar_init(mbar_sm, 1);
        mbar_init(mbar_sm + 8, 1);
    }
    __syncthreads();

    // prefetch tile 0 into buffer 0
    if (tid == 0) {
        mbar_expect_tx(mbar_sm, QB * TM * C2_ * 4);
        #pragma unroll
        for (int q = 0; q < QB; q++)
            bulk_cp(s2d_sm + q * TM * C2_ * 4,
                    in2d + ((long)(n0 + q) * N_) * C2_,
                    TM * C2_ * 4, mbar_sm);
    }

    ulonglong2 a2[2][QB];
    #pragma unroll
    for (int hh = 0; hh < 2; hh++)
        #pragma unroll
        for (int q = 0; q < QB; q++) a2[hh][q] = make_ulonglong2(0ULL, 0ULL);
    u64 acc2b[QB] = {0,0,0,0};
    float srun3[3] = {0.f, 0.f, 0.f};

    for (int t = 0; t < NT; t++) {
        int m0 = t * TM;
        int cur = t & 1;

        // prefetch t+1
        if (tid == 0 && t + 1 < NT) {
            unsigned mb = mbar_sm + (1 - cur) * 8;
            unsigned db = s2d_sm + (1 - cur) * BUFF * 4;
            mbar_expect_tx(mb, QB * TM * C2_ * 4);
            #pragma unroll
            for (int q = 0; q < QB; q++)
                bulk_cp(db + q * TM * C2_ * 4,
                        in2d + ((long)(n0 + q) * N_ + m0 + TM) * C2_,
                        TM * C2_ * 4, mb);
        }

        // preload qk logits (overlap with TMA wait)
        float lg[3];
        if (tid < 256) {
            #pragma unroll
            for (int e = 0; e < 3; e++)
                lg[e] = g_L[((long)(n0 + q2i) * H_ + (u2 * 3 + e)) * N_ + m0 + r2];
        }

        mbar_wait(mbar_sm + cur * 8, (t >> 1) & 1);

        const float* buf = s2d + cur * BUFF;
        const ulonglong2* s2d8 = (const ulonglong2*)buf;  // 32 ul2/row

        // ---- phase 2: fused a2d dot + exp (thread = (q, row, quad), rotated cols) ----
        if (tid < 256) {
            const float* row = buf + (q2i * TM + r2) * C2_;
            float s[12];
            #pragma unroll
            for (int pass = 0; pass < 2; pass++) {
                u64 acc[6];
                #pragma unroll
                for (int hh = 0; hh < 6; hh++) acc[hh] = 0ULL;
                #pragma unroll
                for (int j = 0; j < 8; j++) {
                    int c = u2 + 4 * ((j + r2) & 7);   // conflict-free rotation
                    ulonglong2 d = *(const ulonglong2*)(row + c * 4);
                    #pragma unroll
                    for (int hh = 0; hh < 6; hh++) {
                        ulonglong2 w = swu2[(pass * 6 + hh) * 32 + c];
                        fma2(acc[hh], d.x, w.x);
                        fma2(acc[hh], d.y, w.y);
                    }
                }
                #pragma unroll
                for (int hh = 0; hh < 6; hh++) {
                    float2 a = *(float2*)&acc[hh];
                    float v = a.x + a.y;
                    v += __shfl_xor_sync(0xffffffffu, v, 1);
                    v += __shfl_xor_sync(0xffffffffu, v, 2);
                    s[pass * 6 + hh] = v;
                }
            }
            #pragma unroll
            for (int e = 0; e < 3; e++) {
                int hh = u2 * 3 + e;
                float p = __expf(lg[e] + s[hh] + sb2[hh]);
                srun3[e] += p;
                *(float2*)&spH[(hh * TM + r2) * 8 + 2 * q2i] = make_float2(p, p);
            }
        }
        __syncthreads();

        // ---- phase 3: attn_2d (2 heads/thread, m-split) ----
        {
            int mbeg = mq * (TM / 2);
            #pragma unroll
            for (int mi = mbeg; mi < mbeg + TM / 2; mi++) {
                ulonglong2 pA0 = pbase[(h0 * TM + mi) * 2 + 0];
                ulonglong2 pA1 = pbase[(h0 * TM + mi) * 2 + 1];
                ulonglong2 pB0 = pbase[((h0 + 1) * TM + mi) * 2 + 0];
                ulonglong2 pB1 = pbase[((h0 + 1) * TM + mi) * 2 + 1];
                u64 pH0[4] = {pA0.x, pA0.y, pA1.x, pA1.y};
                u64 pH1[4] = {pB0.x, pB0.y, pB1.x, pB1.y};
                #pragma unroll
                for (int q = 0; q < QB; q++) {
                    ulonglong2 d = s2d8[(q * TM + mi) * 32 + c4];
                    fma2(a2[0][q].x, pH0[q], d.x);
                    fma2(a2[0][q].y, pH0[q], d.y);
                    fma2(a2[1][q].x, pH1[q], d.x);
                    fma2(a2[1][q].y, pH1[q], d.y);
                }
            }
        }

        // ---- phase 2b: merged-v accumulation ----
        {
            const u64* vrow = vm64 + ((long)m0 * H_ + h) * 32 + lane;
            #pragma unroll
            for (int mi = 0; mi < TM; mi++) {
                u64 v = vrow[(long)mi * H_ * 32];
                ulonglong2 pq01 = pbase[(h * TM + mi) * 2 + 0];
                ulonglong2 pq23 = pbase[(h * TM + mi) * 2 + 1];
                fma2(acc2b[0], pq01.x, v);
                fma2(acc2b[1], pq01.y, v);
                fma2(acc2b[2], pq23.x, v);
                fma2(acc2b[3], pq23.y, v);
            }
        }
        __syncthreads();
    }

    // ---- epilogue: srun reduction ----
    if (tid < 256) {
        #pragma unroll
        for (int e = 0; e < 3; e++)
            sred[(q2i * H_ + u2 * 3 + e) * TM + r2] = srun3[e];
    }
    __syncthreads();
    if (tid < QB * H_) {
        float s = 0.f;
        #pragma unroll
        for (int m = 0; m < TM; m++) s += sred[tid * TM + m];
        sinv[tid] = 1.f / s;
    }
    __syncthreads();

    float inv[QB];
    #pragma unroll
    for (int q = 0; q < QB; q++) inv[q] = sinv[q * H_ + h];

    #pragma unroll
    for (int q = 0; q < QB; q++) {
        int n = n0 + q;
        float* f = g_feat + (long)n * NFEAT;
        float2 ac = *(float2*)&acc2b[q];
        ac.x *= inv[q]; ac.y *= inv[q];
        if (lane < 8) {
            f[h * 16 + 2 * lane]     = ac.x;
            f[h * 16 + 2 * lane + 1] = ac.y;
        }
        __syncwarp();
        if (lane >= 8 && lane < 20) {
            spH[h * 64 + 2 * (lane - 8)]     = ac.x;
            spH[h * 64 + 2 * (lane - 8) + 1] = ac.y;
        }
        __syncwarp();
        if (lane < 8) {
            int p = lane;
            float gx = spH[h * 64 + p * 3 + 0] - trans[n * 3 + 0];
            float gy = spH[h * 64 + p * 3 + 1] - trans[n * 3 + 1];
            float gz = spH[h * 64 + p * 3 + 2] - trans[n * 3 + 2];
            float lx = rot[n*9+0]*gx + rot[n*9+3]*gy + rot[n*9+6]*gz;
            float ly = rot[n*9+1]*gx + rot[n*9+4]*gy + rot[n*9+7]*gz;
            float lz = rot[n*9+2]*gx + rot[n*9+5]*gy + rot[n*9+8]*gz;
            float d  = sqrtf(1e-8f + lx*lx + ly*ly + lz*lz);
            f[192 + h * 8 + p] = lx;
            f[288 + h * 8 + p] = ly;
            f[384 + h * 8 + p] = lz;
            f[480 + h * 8 + p] = d;
        }
        __syncwarp();
    }
    __syncthreads();

    float4* red = (float4*)s2d;
    #pragma unroll
    for (int hh = 0; hh < 2; hh++) {
        __syncthreads();
        #pragma unroll
        for (int q = 0; q < QB; q++) {
            u64 iv2 = pack2(sinv[q * H_ + h0 + hh]);
            u64 vx = a2[hh][q].x, vy = a2[hh][q].y;
            mul2(vx, iv2); mul2(vy, iv2);
            float2 lo = *(float2*)&vx;
            float2 hi = *(float2*)&vy;
            red[(q * 2 + mq) * 192 + hp * 32 + c4] = make_float4(lo.x, lo.y, hi.x, hi.y);
        }
        __syncthreads();
        if (mq == 0) {
            #pragma unroll
            for (int q = 0; q < QB; q++) {
                float4 a = red[(q * 2    ) * 192 + hp * 32 + c4];
                float4 b = red[(q * 2 + 1) * 192 + hp * 32 + c4];
                a.x += b.x; a.y += b.y; a.z += b.z; a.w += b.w;
                *(float4*)&g_feat[(long)(n0 + q) * NFEAT + 576 + (h0 + hh) * 128 + c4 * 4] = a;
            }
        }
    }
}

// ---------------- kernel F: output GEMM ----------------
__global__ __launch_bounds__(1024) void out_gemm_kernel(
    const float* __restrict__ B, const float* __restrict__ bias,
    float* __restrict__ C)
{
    __shared__ float As[4][16][64];
    __shared__ float Bs[4][16][36];
    int tid = threadIdx.x;
    int g = tid >> 8;
    int t = tid & 255;
    int bm = blockIdx.x * 64, bn = blockIdx.y * 32;
    int tx = t & 15, ty = t >> 4;
    int lm = t >> 2, lk4 = (t & 3) * 4;
    u64 acc[4] = {0,0,0,0};

    int kbase = g * 528;
    for (int kk0 = 0; kk0 < 528; kk0 += 16) {
        int k0 = kbase + kk0;
        float4 av = *(const float4*)&g_feat[(long)(bm + lm) * NFEAT + k0 + lk4];
        As[g][lk4+0][lm] = av.x; As[g][lk4+1][lm] = av.y;
        As[g][lk4+2][lm] = av.z; As[g][lk4+3][lm] = av.w;
        if (t < 128) {
            int bk = t >> 3, bn4 = (t & 7) * 4;
            float4 bv = *(const float4*)&B[(long)(k0 + bk) * COUT_ + bn + bn4];
            *(float4*)&Bs[g][bk][bn4] = bv;
        }
        __syncthreads();
        #pragma unroll
        for (int kk = 0; kk < 16; kk++) {
            float4 a4 = *(const float4*)&As[g][kk][ty * 4];
            u64 b = *(const u64*)&Bs[g][kk][tx * 2];
            fma2(acc[0], pack2(a4.x), b);
            fma2(acc[1], pack2(a4.y), b);
            fma2(acc[2], pack2(a4.z), b);
            fma2(acc[3], pack2(a4.w), b);
        }
        __syncthreads();
    }

    float* red = &As[0][0][0];
    #pragma unroll
    for (int r = 0; r < 2; r++) {
        __syncthreads();
        if (g > 0) {
            float2 p0 = *(float2*)&acc[r * 2];
            float2 p1 = *(float2*)&acc[r * 2 + 1];
            *(float4*)&red[((g - 1) * 256 + t) * 4] = make_float4(p0.x, p0.y, p1.x, p1.y);
        }
        __syncthreads();
        if (g == 0) {
            #pragma unroll
            for (int gg = 0; gg < 3; gg++) {
                float4 v = *(float4*)&red[(gg * 256 + t) * 4];
                float2 p0 = *(float2*)&acc[r * 2];
                float2 p1 = *(float2*)&acc[r * 2 + 1];
                p0.x += v.x; p0.y += v.y; p1.x += v.z; p1.y += v.w;
                *(float2*)&acc[r * 2]     = p0;
                *(float2*)&acc[r * 2 + 1] = p1;
            }
        }
    }
    if (g == 0) {
        float b0 = bias[bn + tx * 2], b1 = bias[bn + tx * 2 + 1];
        #pragma unroll
        for (int i = 0; i < 4; i++) {
            float2 v = *(float2*)&acc[i];
            v.x += b0; v.y += b1;
            *(float2*)&C[(long)(bm + ty * 4 + i) * COUT_ + bn + tx * 2] = v;
        }
    }
}

// ---------------- launch ----------------
extern "C" void kernel_launch(void* const* d_in, const int* in_sizes, int n_in,
                              void* d_out, int out_size)
{
    const float* inputs_1d = (const float*)d_in[0];
    const float* inputs_2d = (const float*)d_in[1];
    const float* mask      = (const float*)d_in[2];
    const float* rot       = (const float*)d_in[3];
    const float* trans     = (const float*)d_in[4];
    const float* wq        = (const float*)d_in[5];
    const float* bq        = (const float*)d_in[6];
    const float* wkv       = (const float*)d_in[7];
    const float* bkv       = (const float*)d_in[8];
    const float* wqp       = (const float*)d_in[9];
    const float* bqp       = (const float*)d_in[10];
    const float* wkvp      = (const float*)d_in[11];
    const float* bkvp      = (const float*)d_in[12];
    const float* w2d       = (const float*)d_in[13];
    const float* b2d       = (const float*)d_in[14];
    const float* tpw       = (const float*)d_in[15];
    const float* wout      = (const float*)d_in[16];
    const float* bout      = (const float*)d_in[17];
    float* out = (float*)d_out;

    proj_gemm_kernel<<<dim3(16, 18), 256>>>(inputs_1d, wq, bq, wkv, bkv,
                                            wqp, bqp, wkvp, bkvp);
    transform_kernel<<<N_, 192>>>(rot, trans, tpw);

    qk_kernel<<<dim3(16, 16, 12), 256>>>(mask);

    int smemE = (2 * BUFF + H_ * TM * 8 + H_ * C2_ + QB * H_ * TM +
                 H_ + QB * H_ + 4) * (int)sizeof(float);
    cudaFuncSetAttribute(attn_kernel, cudaFuncAttributeMaxDynamicSharedMemorySize, smemE);
    attn_kernel<<<N_ / QB, 384, smemE>>>(inputs_2d, rot, trans, w2d, b2d);

    out_gemm_kernel<<<dim3(16, 12), 1024>>>(wout, bout, out);
}

// round 17
// speedup vs baseline: 1.2408x; 1.2408x over previous
#include <cuda_runtime.h>
#include <math.h>

#define N_    1024
#define H_    12
#define C1_   384
#define C2_   128
#define COUT_ 384
#define NPROJ 1152
#define NFEAT 2112
#define QB    4
#define TM    16
#define NT    (N_ / TM)
#define BUFF  (QB * TM * C2_)      // 8192 floats = 32KB per buffer

#define W2DS 0.5773502691896258f
#define SCW  0.14433756729740643f
#define PTW  0.1360827634879543f

typedef unsigned long long u64;

__device__ __forceinline__ void fma2(u64& acc, u64 a, u64 b) {
    asm("fma.rn.f32x2 %0, %1, %2, %0;" : "+l"(acc) : "l"(a), "l"(b));
}
__device__ __forceinline__ void mul2(u64& a, u64 b) {
    asm("mul.rn.f32x2 %0, %0, %1;" : "+l"(a) : "l"(b));
}
__device__ __forceinline__ u64 pack2(float a) {
    u64 r;
    asm("mov.b64 %0, {%1, %1};" : "=l"(r) : "f"(a));
    return r;
}
__device__ __forceinline__ unsigned smem_u32(const void* p) {
    return (unsigned)__cvta_generic_to_shared(p);
}
__device__ __forceinline__ void bulk_cp(unsigned dst, const void* src,
                                        unsigned bytes, unsigned mbar) {
    asm volatile(
        "cp.async.bulk.shared::cta.global.mbarrier::complete_tx::bytes "
        "[%0], [%1], %2, [%3];"
        :: "r"(dst), "l"(src), "r"(bytes), "r"(mbar) : "memory");
}
__device__ __forceinline__ void mbar_init(unsigned mbar, unsigned cnt) {
    asm volatile("mbarrier.init.shared.b64 [%0], %1;" :: "r"(mbar), "r"(cnt) : "memory");
}
__device__ __forceinline__ void mbar_expect_tx(unsigned mbar, unsigned bytes) {
    asm volatile("mbarrier.arrive.expect_tx.shared.b64 _, [%0], %1;"
                 :: "r"(mbar), "r"(bytes) : "memory");
}
__device__ __forceinline__ void mbar_wait(unsigned mbar, unsigned parity) {
    asm volatile(
        "{\n\t"
        ".reg .pred P1;\n\t"
        "WAIT_LOOP_%=:\n\t"
        "mbarrier.try_wait.parity.acquire.cta.shared::cta.b64 P1, [%0], %1, 0x989680;\n\t"
        "@P1 bra.uni WAIT_DONE_%=;\n\t"
        "bra.uni WAIT_LOOP_%=;\n\t"
        "WAIT_DONE_%=:\n\t"
        "}"
        :: "r"(mbar), "r"(parity) : "memory");
}

// ---------------- scratch ----------------
__device__ float g_proj [N_ * NPROJ];
__device__ float g_qpt  [N_ * 144];
__device__ float g_kpt  [N_ * 144];
__device__ float g_vpt  [N_ * 288];
__device__ float g_qaug [N_ * H_ * 32];
__device__ float g_kaug [N_ * H_ * 32];
__device__ float g_P    [(long)N_ * H_ * 1024];   // a2d base -> probs after qk
__device__ float g_vm   [(long)N_ * H_ * 64];
__device__ float g_feat [(long)N_ * NFEAT];

// ---------------- kernel A: fused projection GEMM ----------------
__global__ __launch_bounds__(256) void proj_gemm_kernel(
    const float* __restrict__ A,
    const float* __restrict__ wq,  const float* __restrict__ bq,
    const float* __restrict__ wkv, const float* __restrict__ bkv,
    const float* __restrict__ wqp, const float* __restrict__ bqp,
    const float* __restrict__ wkvp,const float* __restrict__ bkvp)
{
    __shared__ float As[16][64];
    __shared__ float Bs[16][68];
    int bm = blockIdx.x * 64, bn = blockIdx.y * 64;
    int tid = threadIdx.x;
    int tx = tid & 15, ty = tid >> 4;
    int lm = tid >> 2, lk4 = (tid & 3) * 4;
    int bk = tid >> 4, bn4 = (tid & 15) * 4;
    u64 acc01[4] = {0,0,0,0}, acc23[4] = {0,0,0,0};

    for (int k0 = 0; k0 < C1_; k0 += 16) {
        float4 av = *(const float4*)&A[(bm + lm) * C1_ + k0 + lk4];
        As[lk4+0][lm] = av.x; As[lk4+1][lm] = av.y;
        As[lk4+2][lm] = av.z; As[lk4+3][lm] = av.w;
        int kg = k0 + bk;
        #pragma unroll
        for (int jj = 0; jj < 4; jj++) {
            int j = bn + bn4 + jj;
            float v;
            if      (j < 192) v = wq  [kg * 192 + j];
            else if (j < 576) v = wkv [kg * 384 + (j - 192)];
            else if (j < 720) v = wqp [kg * 144 + (j - 576)];
            else              v = wkvp[kg * 432 + (j - 720)];
            Bs[bk][bn4 + jj] = v;
        }
        __syncthreads();
        #pragma unroll
        for (int kk = 0; kk < 16; kk++) {
            float4 a4 = *(const float4*)&As[kk][ty * 4];
            ulonglong2 b2 = *(const ulonglong2*)&Bs[kk][tx * 4];
            float a[4] = {a4.x, a4.y, a4.z, a4.w};
            #pragma unroll
            for (int i = 0; i < 4; i++) {
                u64 ai = pack2(a[i]);
                fma2(acc01[i], ai, b2.x);
                fma2(acc23[i], ai, b2.y);
            }
        }
        __syncthreads();
    }
    #pragma unroll
    for (int i = 0; i < 4; i++) {
        float2 lo = *(float2*)&acc01[i];
        float2 hi = *(float2*)&acc23[i];
        float accv[4] = {lo.x, lo.y, hi.x, hi.y};
        #pragma unroll
        for (int j = 0; j < 4; j++) {
            int jg = bn + tx * 4 + j;
            float bias;
            if      (jg < 192) bias = bq  [jg];
            else if (jg < 576) bias = bkv [jg - 192];
            else if (jg < 720) bias = bqp [jg - 576];
            else               bias = bkvp[jg - 720];
            g_proj[(bm + ty * 4 + i) * NPROJ + jg] = accv[j] + bias;
        }
    }
}

// ---------------- kernel B: transform + aug + merged v ----------------
__global__ __launch_bounds__(192) void transform_kernel(
    const float* __restrict__ rot, const float* __restrict__ trans,
    const float* __restrict__ tpw)
{
    int n = blockIdx.x;
    int tid = threadIdx.x;
    __shared__ float sn2[192];

    const float* pr = g_proj + n * NPROJ;
    float r00 = rot[n*9+0], r01 = rot[n*9+1], r02 = rot[n*9+2];
    float r10 = rot[n*9+3], r11 = rot[n*9+4], r12 = rot[n*9+5];
    float r20 = rot[n*9+6], r21 = rot[n*9+7], r22 = rot[n*9+8];
    float t0 = trans[n*3+0], t1 = trans[n*3+1], t2 = trans[n*3+2];

    float nrm = 0.f;
    if (tid < 48) {
        int pp = tid;
        float px = pr[576 +       pp];
        float py = pr[576 +  48 + pp];
        float pz = pr[576 +  96 + pp];
        float gx = r00*px + r01*py + r02*pz + t0;
        float gy = r10*px + r11*py + r12*pz + t1;
        float gz = r20*px + r21*py + r22*pz + t2;
        int h = pp >> 2, p = pp & 3;
        float* o = g_qpt + n * 144 + h * 12 + p * 3;
        o[0] = gx; o[1] = gy; o[2] = gz;
        nrm = gx*gx + gy*gy + gz*gz;
    } else {
        int pp = tid - 48;
        float px = pr[720 +       pp];
        float py = pr[720 + 144 + pp];
        float pz = pr[720 + 288 + pp];
        float gx = r00*px + r01*py + r02*pz + t0;
        float gy = r10*px + r11*py + r12*pz + t1;
        float gz = r20*px + r21*py + r22*pz + t2;
        int h = pp / 12, r = pp % 12;
        if (r < 4) {
            float* o = g_kpt + n * 144 + h * 12 + r * 3;
            o[0] = gx; o[1] = gy; o[2] = gz;
            nrm = gx*gx + gy*gy + gz*gz;
        } else {
            float* o = g_vpt + n * 288 + h * 24 + (r - 4) * 3;
            o[0] = gx; o[1] = gy; o[2] = gz;
        }
    }
    sn2[tid] = nrm;
    __syncthreads();
    if (tid < H_) {
        int h = tid;
        float q2 = 0.f, k2 = 0.f;
        #pragma unroll
        for (int p = 0; p < 4; p++) q2 += sn2[h * 4 + p];
        #pragma unroll
        for (int r = 0; r < 4; r++) k2 += sn2[48 + h * 12 + r];

        float tp = tpw[h];
        float spv = tp > 20.f ? tp : log1pf(__expf(tp));
        float pw = PTW * spv;

        float* qa = g_qaug + (n * H_ + h) * 32;
        float* ka = g_kaug + (n * H_ + h) * 32;
        #pragma unroll
        for (int c = 0; c < 16; c++) {
            qa[c] = SCW * pr[h * 16 + c];
            ka[c] = pr[192 + h * 32 + c];
        }
        #pragma unroll
        for (int c = 0; c < 12; c++) {
            qa[16 + c] = pw * g_qpt[n * 144 + h * 12 + c];
            ka[16 + c] = g_kpt[n * 144 + h * 12 + c];
        }
        qa[28] = -0.5f * pw * q2; qa[29] = 1.f; qa[30] = 0.f; qa[31] = 0.f;
        ka[28] = 1.f; ka[29] = -0.5f * pw * k2; ka[30] = 0.f; ka[31] = 0.f;

        float2* vm = (float2*)&g_vm[((long)n * H_ + h) * 64];
        #pragma unroll
        for (int j = 0; j < 8; j++)
            vm[j] = make_float2(pr[192 + h * 32 + 16 + 2*j],
                                pr[192 + h * 32 + 16 + 2*j + 1]);
        #pragma unroll
        for (int j = 8; j < 20; j++)
            vm[j] = make_float2(g_vpt[n * 288 + h * 24 + 2*(j-8)],
                                g_vpt[n * 288 + h * 24 + 2*(j-8) + 1]);
        #pragma unroll
        for (int j = 20; j < 32; j++)
            vm[j] = make_float2(0.f, 0.f);
    }
}

// ---------------- kernel C: a2d streaming (TMA stage, 2 rows/thread) ----------------
__global__ void __launch_bounds__(256, 3) a2d_kernel(
    const float* __restrict__ in2d, const float* __restrict__ w2d,
    const float* __restrict__ b2d)
{
    extern __shared__ float smC[];
    float* sd = smC;                    // 128 rows * 128 floats = 64KB
    float* sw = smC + 128 * C2_;        // 12*128
    u64*   mb = (u64*)(sw + H_ * C2_);  // mbarrier

    int tid = threadIdx.x;
    int n   = blockIdx.y;
    int m0  = blockIdx.x * 128;

    unsigned sd_sm = smem_u32(sd);
    unsigned mb_sm = smem_u32(mb);

    if (tid == 0) mbar_init(mb_sm, 1);
    for (int i = tid; i < H_ * C2_; i += 256)
        sw[i] = w2d[(i & 127) * H_ + (i >> 7)] * W2DS;
    __syncthreads();
    if (tid == 0) {
        mbar_expect_tx(mb_sm, 128 * C2_ * 4);
        bulk_cp(sd_sm, in2d + ((long)n * N_ + m0) * C2_, 128 * C2_ * 4, mb_sm);
    }

    int rp = tid >> 2;          // row pair base 0..63
    int u  = tid & 3;           // quad lane

    mbar_wait(mb_sm, 0);

    const ulonglong2* swu2 = (const ulonglong2*)sw;
    const float* rowA = sd + rp * C2_;
    const float* rowB = sd + (rp + 64) * C2_;

    u64 accA[12], accB[12];
    #pragma unroll
    for (int h = 0; h < 12; h++) { accA[h] = 0ULL; accB[h] = 0ULL; }

    #pragma unroll
    for (int k = 0; k < 8; k++) {
        int c = u + 4 * ((k + rp) & 7);     // conflict-free rotation
        ulonglong2 dA = *(const ulonglong2*)(rowA + c * 4);
        ulonglong2 dB = *(const ulonglong2*)(rowB + c * 4);
        #pragma unroll
        for (int h = 0; h < 12; h++) {
            ulonglong2 w = swu2[h * 32 + c];
            fma2(accA[h], dA.x, w.x);
            fma2(accA[h], dA.y, w.y);
            fma2(accB[h], dB.x, w.x);
            fma2(accB[h], dB.y, w.y);
        }
    }

    #pragma unroll
    for (int h = 0; h < 12; h++) {
        float2 aA = *(float2*)&accA[h];
        float2 aB = *(float2*)&accB[h];
        float vA = aA.x + aA.y;
        float vB = aB.x + aB.y;
        vA += __shfl_xor_sync(0xffffffffu, vA, 1);
        vA += __shfl_xor_sync(0xffffffffu, vA, 2);
        vB += __shfl_xor_sync(0xffffffffu, vB, 1);
        vB += __shfl_xor_sync(0xffffffffu, vB, 2);
        if (h / 3 == u) {   // quad lane u writes heads 3u..3u+2
            float bb = b2d[h] * W2DS;
            g_P[((long)n * H_ + h) * N_ + m0 + rp]      = vA + bb;
            g_P[((long)n * H_ + h) * N_ + m0 + rp + 64] = vB + bb;
        }
    }
}

// ---------------- kernel D: qk GEMM + mask + EXP (f32x2 inner) ----------------
__global__ __launch_bounds__(256) void qk_kernel(const float* __restrict__ mask)
{
    __shared__ float Aq[32][68];
    __shared__ float Bk[32][68];
    int h  = blockIdx.z;
    int nb = blockIdx.y * 64, mb = blockIdx.x * 64;
    int tid = threadIdx.x;

    for (int i = tid; i < 64 * 8; i += 256) {
        int row = i >> 3, k4 = (i & 7) * 4;
        float4 q = *(const float4*)&g_qaug[((nb + row) * H_ + h) * 32 + k4];
        Aq[k4+0][row] = q.x; Aq[k4+1][row] = q.y; Aq[k4+2][row] = q.z; Aq[k4+3][row] = q.w;
        float4 k = *(const float4*)&g_kaug[((mb + row) * H_ + h) * 32 + k4];
        Bk[k4+0][row] = k.x; Bk[k4+1][row] = k.y; Bk[k4+2][row] = k.z; Bk[k4+3][row] = k.w;
    }
    __syncthreads();

    int tx = tid & 15, ty = tid >> 4;
    u64 acc01[4] = {0,0,0,0}, acc23[4] = {0,0,0,0};
    #pragma unroll
    for (int k = 0; k < 32; k++) {
        float4 a4 = *(const float4*)&Aq[k][ty * 4];
        ulonglong2 b2 = *(const ulonglong2*)&Bk[k][tx * 4];
        float a[4] = {a4.x, a4.y, a4.z, a4.w};
        #pragma unroll
        for (int i = 0; i < 4; i++) {
            u64 ai = pack2(a[i]);
            fma2(acc01[i], ai, b2.x);
            fma2(acc23[i], ai, b2.y);
        }
    }
    float mm[4], mn[4];
    #pragma unroll
    for (int j = 0; j < 4; j++) mm[j] = mask[mb + tx * 4 + j];
    #pragma unroll
    for (int i = 0; i < 4; i++) mn[i] = mask[nb + ty * 4 + i];

    #pragma unroll
    for (int i = 0; i < 4; i++) {
        float2 lo = *(float2*)&acc01[i];
        float2 hi = *(float2*)&acc23[i];
        float* p = &g_P[((long)(nb + ty * 4 + i) * H_ + h) * N_ + mb + tx * 4];
        float4 L4 = *(float4*)p;
        L4.x = __expf(L4.x + lo.x - 100000.f * (1.f - mn[i] * mm[0]));
        L4.y = __expf(L4.y + lo.y - 100000.f * (1.f - mn[i] * mm[1]));
        L4.z = __expf(L4.z + hi.x - 100000.f * (1.f - mn[i] * mm[2]));
        L4.w = __expf(L4.w + hi.y - 100000.f * (1.f - mn[i] * mm[3]));
        *(float4*)p = L4;
    }
}

// ---------------- kernel E: attention (TMA bulk double-buffered, local srun) ----------------
__global__ void __launch_bounds__(384, 2) attn_kernel(
    const float* __restrict__ in2d,
    const float* __restrict__ rot, const float* __restrict__ trans)
{
    extern __shared__ float sm[];
    float* s2d  = sm;                      // 2 * 8192 floats
    float* spH  = sm + 2 * BUFF;           // 12*16*8 = 1536
    float* sinv = spH + H_ * TM * 8;       // 48
    u64*   mbar = (u64*)(sinv + QB * H_);  // 2 mbarriers

    int tid  = threadIdx.x;
    int h    = tid >> 5;
    int lane = tid & 31;
    int n0   = blockIdx.x * QB;

    int c4 = tid & 31;
    int hp = (tid >> 5) % 6;
    int mq = tid / 192;
    int h0 = hp * 2;

    unsigned s2d_sm  = smem_u32(s2d);
    unsigned mbar_sm = smem_u32(mbar);
    const u64* vm64 = (const u64*)g_vm;
    const ulonglong2* pbase = (const ulonglong2*)spH;

    if (tid == 0) {
        mbar_init(mbar_sm, 1);
        mbar_init(mbar_sm + 8, 1);
    }
    __syncthreads();

    if (tid == 0) {
        mbar_expect_tx(mbar_sm, QB * TM * C2_ * 4);
        #pragma unroll
        for (int q = 0; q < QB; q++)
            bulk_cp(s2d_sm + q * TM * C2_ * 4,
                    in2d + ((long)(n0 + q) * N_) * C2_,
                    TM * C2_ * 4, mbar_sm);
    }

    ulonglong2 a2[2][QB];
    #pragma unroll
    for (int hh = 0; hh < 2; hh++)
        #pragma unroll
        for (int q = 0; q < QB; q++) a2[hh][q] = make_ulonglong2(0ULL, 0ULL);
    u64 acc2b[QB] = {0,0,0,0};
    float srun[QB] = {0.f, 0.f, 0.f, 0.f};

    for (int t = 0; t < NT; t++) {
        int m0 = t * TM;
        int cur = t & 1;

        if (tid == 0 && t + 1 < NT) {
            unsigned mb = mbar_sm + (1 - cur) * 8;
            unsigned db = s2d_sm + (1 - cur) * BUFF * 4;
            mbar_expect_tx(mb, QB * TM * C2_ * 4);
            #pragma unroll
            for (int q = 0; q < QB; q++)
                bulk_cp(db + q * TM * C2_ * 4,
                        in2d + ((long)(n0 + q) * N_ + m0 + TM) * C2_,
                        TM * C2_ * 4, mb);
        }

        if (lane < TM) {
            int m = m0 + lane;
            float pv[QB];
            #pragma unroll
            for (int q = 0; q < QB; q++) {
                pv[q] = g_P[((long)(n0 + q) * H_ + h) * N_ + m];
                srun[q] += pv[q];
            }
            float* dst = &spH[(h * TM + lane) * 8];
            *(float4*)dst       = make_float4(pv[0], pv[0], pv[1], pv[1]);
            *(float4*)(dst + 4) = make_float4(pv[2], pv[2], pv[3], pv[3]);
        }

        mbar_wait(mbar_sm + cur * 8, (t >> 1) & 1);
        __syncthreads();

        const float* buf = s2d + cur * BUFF;
        const ulonglong2* s2d8 = (const ulonglong2*)buf;

        {
            int mbeg = mq * (TM / 2);
            #pragma unroll
            for (int mi = mbeg; mi < mbeg + TM / 2; mi++) {
                ulonglong2 pA0 = pbase[(h0 * TM + mi) * 2 + 0];
                ulonglong2 pA1 = pbase[(h0 * TM + mi) * 2 + 1];
                ulonglong2 pB0 = pbase[((h0 + 1) * TM + mi) * 2 + 0];
                ulonglong2 pB1 = pbase[((h0 + 1) * TM + mi) * 2 + 1];
                u64 pH0[4] = {pA0.x, pA0.y, pA1.x, pA1.y};
                u64 pH1[4] = {pB0.x, pB0.y, pB1.x, pB1.y};
                #pragma unroll
                for (int q = 0; q < QB; q++) {
                    ulonglong2 d = s2d8[(q * TM + mi) * 32 + c4];
                    fma2(a2[0][q].x, pH0[q], d.x);
                    fma2(a2[0][q].y, pH0[q], d.y);
                    fma2(a2[1][q].x, pH1[q], d.x);
                    fma2(a2[1][q].y, pH1[q], d.y);
                }
            }
        }

        {
            const u64* vrow = vm64 + ((long)m0 * H_ + h) * 32 + lane;
            #pragma unroll
            for (int mi = 0; mi < TM; mi++) {
                u64 v = vrow[(long)mi * H_ * 32];
                ulonglong2 pq01 = pbase[(h * TM + mi) * 2 + 0];
                ulonglong2 pq23 = pbase[(h * TM + mi) * 2 + 1];
                fma2(acc2b[0], pq01.x, v);
                fma2(acc2b[1], pq01.y, v);
                fma2(acc2b[2], pq23.x, v);
                fma2(acc2b[3], pq23.y, v);
            }
        }
        __syncthreads();
    }

    float inv[QB];
    #pragma unroll
    for (int q = 0; q < QB; q++) {
        float s = srun[q];
        #pragma unroll
        for (int o = 16; o > 0; o >>= 1)
            s += __shfl_xor_sync(0xffffffffu, s, o);
        inv[q] = 1.f / s;
        if (lane == 0) sinv[q * H_ + h] = inv[q];
    }
    #pragma unroll
    for (int q = 0; q < QB; q++) {
        int n = n0 + q;
        float* f = g_feat + (long)n * NFEAT;
        float2 ac = *(float2*)&acc2b[q];
        ac.x *= inv[q]; ac.y *= inv[q];
        if (lane < 8) {
            f[h * 16 + 2 * lane]     = ac.x;
            f[h * 16 + 2 * lane + 1] = ac.y;
        }
        __syncwarp();
        if (lane >= 8 && lane < 20) {
            spH[h * 64 + 2 * (lane - 8)]     = ac.x;
            spH[h * 64 + 2 * (lane - 8) + 1] = ac.y;
        }
        __syncwarp();
        if (lane < 8) {
            int p = lane;
            float gx = spH[h * 64 + p * 3 + 0] - trans[n * 3 + 0];
            float gy = spH[h * 64 + p * 3 + 1] - trans[n * 3 + 1];
            float gz = spH[h * 64 + p * 3 + 2] - trans[n * 3 + 2];
            float lx = rot[n*9+0]*gx + rot[n*9+3]*gy + rot[n*9+6]*gz;
            float ly = rot[n*9+1]*gx + rot[n*9+4]*gy + rot[n*9+7]*gz;
            float lz = rot[n*9+2]*gx + rot[n*9+5]*gy + rot[n*9+8]*gz;
            float d  = sqrtf(1e-8f + lx*lx + ly*ly + lz*lz);
            f[192 + h * 8 + p] = lx;
            f[288 + h * 8 + p] = ly;
            f[384 + h * 8 + p] = lz;
            f[480 + h * 8 + p] = d;
        }
        __syncwarp();
    }
    __syncthreads();

    float4* red = (float4*)s2d;
    #pragma unroll
    for (int hh = 0; hh < 2; hh++) {
        __syncthreads();
        #pragma unroll
        for (int q = 0; q < QB; q++) {
            u64 iv2 = pack2(sinv[q * H_ + h0 + hh]);
            u64 vx = a2[hh][q].x, vy = a2[hh][q].y;
            mul2(vx, iv2); mul2(vy, iv2);
            float2 lo = *(float2*)&vx;
            float2 hi = *(float2*)&vy;
            red[(q * 2 + mq) * 192 + hp * 32 + c4] = make_float4(lo.x, lo.y, hi.x, hi.y);
        }
        __syncthreads();
        if (mq == 0) {
            #pragma unroll
            for (int q = 0; q < QB; q++) {
                float4 a = red[(q * 2    ) * 192 + hp * 32 + c4];
                float4 b = red[(q * 2 + 1) * 192 + hp * 32 + c4];
                a.x += b.x; a.y += b.y; a.z += b.z; a.w += b.w;
                *(float4*)&g_feat[(long)(n0 + q) * NFEAT + 576 + (h0 + hh) * 128 + c4 * 4] = a;
            }
        }
    }
}

// ---------------- kernel F: output GEMM ----------------
__global__ __launch_bounds__(1024) void out_gemm_kernel(
    const float* __restrict__ B, const float* __restrict__ bias,
    float* __restrict__ C)
{
    __shared__ float As[4][16][64];
    __shared__ float Bs[4][16][36];
    int tid = threadIdx.x;
    int g = tid >> 8;
    int t = tid & 255;
    int bm = blockIdx.x * 64, bn = blockIdx.y * 32;
    int tx = t & 15, ty = t >> 4;
    int lm = t >> 2, lk4 = (t & 3) * 4;
    u64 acc[4] = {0,0,0,0};

    int kbase = g * 528;
    for (int kk0 = 0; kk0 < 528; kk0 += 16) {
        int k0 = kbase + kk0;
        float4 av = *(const float4*)&g_feat[(long)(bm + lm) * NFEAT + k0 + lk4];
        As[g][lk4+0][lm] = av.x; As[g][lk4+1][lm] = av.y;
        As[g][lk4+2][lm] = av.z; As[g][lk4+3][lm] = av.w;
        if (t < 128) {
            int bk = t >> 3, bn4 = (t & 7) * 4;
            float4 bv = *(const float4*)&B[(long)(k0 + bk) * COUT_ + bn + bn4];
            *(float4*)&Bs[g][bk][bn4] = bv;
        }
        __syncthreads();
        #pragma unroll
        for (int kk = 0; kk < 16; kk++) {
            float4 a4 = *(const float4*)&As[g][kk][ty * 4];
            u64 b = *(const u64*)&Bs[g][kk][tx * 2];
            fma2(acc[0], pack2(a4.x), b);
            fma2(acc[1], pack2(a4.y), b);
            fma2(acc[2], pack2(a4.z), b);
            fma2(acc[3], pack2(a4.w), b);
        }
        __syncthreads();
    }

    float* red = &As[0][0][0];
    #pragma unroll
    for (int r = 0; r < 2; r++) {
        __syncthreads();
        if (g > 0) {
            float2 p0 = *(float2*)&acc[r * 2];
            float2 p1 = *(float2*)&acc[r * 2 + 1];
            *(float4*)&red[((g - 1) * 256 + t) * 4] = make_float4(p0.x, p0.y, p1.x, p1.y);
        }
        __syncthreads();
        if (g == 0) {
            #pragma unroll
            for (int gg = 0; gg < 3; gg++) {
                float4 v = *(float4*)&red[(gg * 256 + t) * 4];
                float2 p0 = *(float2*)&acc[r * 2];
                float2 p1 = *(float2*)&acc[r * 2 + 1];
                p0.x += v.x; p0.y += v.y; p1.x += v.z; p1.y += v.w;
                *(float2*)&acc[r * 2]     = p0;
                *(float2*)&acc[r * 2 + 1] = p1;
            }
        }
    }
    if (g == 0) {
        float b0 = bias[bn + tx * 2], b1 = bias[bn + tx * 2 + 1];
        #pragma unroll
        for (int i = 0; i < 4; i++) {
            float2 v = *(float2*)&acc[i];
            v.x += b0; v.y += b1;
            *(float2*)&C[(long)(bm + ty * 4 + i) * COUT_ + bn + tx * 2] = v;
        }
    }
}

// ---------------- launch ----------------
extern "C" void kernel_launch(void* const* d_in, const int* in_sizes, int n_in,
                              void* d_out, int out_size)
{
    const float* inputs_1d = (const float*)d_in[0];
    const float* inputs_2d = (const float*)d_in[1];
    const float* mask      = (const float*)d_in[2];
    const float* rot       = (const float*)d_in[3];
    const float* trans     = (const float*)d_in[4];
    const float* wq        = (const float*)d_in[5];
    const float* bq        = (const float*)d_in[6];
    const float* wkv       = (const float*)d_in[7];
    const float* bkv       = (const float*)d_in[8];
    const float* wqp       = (const float*)d_in[9];
    const float* bqp       = (const float*)d_in[10];
    const float* wkvp      = (const float*)d_in[11];
    const float* bkvp      = (const float*)d_in[12];
    const float* w2d       = (const float*)d_in[13];
    const float* b2d       = (const float*)d_in[14];
    const float* tpw       = (const float*)d_in[15];
    const float* wout      = (const float*)d_in[16];
    const float* bout      = (const float*)d_in[17];
    float* out = (float*)d_out;

    proj_gemm_kernel<<<dim3(16, 18), 256>>>(inputs_1d, wq, bq, wkv, bkv,
                                            wqp, bqp, wkvp, bkvp);
    transform_kernel<<<N_, 192>>>(rot, trans, tpw);

    int smemC = (128 * C2_ + H_ * C2_ + 4) * (int)sizeof(float);
    cudaFuncSetAttribute(a2d_kernel, cudaFuncAttributeMaxDynamicSharedMemorySize, smemC);
    a2d_kernel<<<dim3(8, N_), 256, smemC>>>(inputs_2d, w2d, b2d);

    qk_kernel<<<dim3(16, 16, 12), 256>>>(mask);

    int smemE = (2 * BUFF + H_ * TM * 8 + QB * H_ + 4) * (int)sizeof(float);
    cudaFuncSetAttribute(attn_kernel, cudaFuncAttributeMaxDynamicSharedMemorySize, smemE);
    attn_kernel<<<N_ / QB, 384, smemE>>>(inputs_2d, rot, trans);

    out_gemm_kernel<<<dim3(16, 12), 1024>>>(wout, bout, out);
}